// round 14
// baseline (speedup 1.0000x reference)
#include <cuda_runtime.h>

// Problem constants (fixed by the reference: N=16384, D=2, H=128)
constexpr int N_ROWS = 16384;
constexpr int H      = 128;
constexpr int NHi    = N_ROWS * H;          // floats per [N,H] tensor

constexpr int THREADS = 256;
constexpr int WPB     = 8;                           // warps per block
constexpr int SBLOCKS = 1024;                        // streaming blocks
constexpr int TW      = SBLOCKS * WPB;               // 8192 warps
constexpr int RPW     = N_ROWS / TW;                 // 2 rows/warp
constexpr int GRID    = SBLOCKS + 1;                 // + 1 waiter block

// Occupancy ballast: 46 KB static shared per block -> 4 CTAs/SM.
// (228 KB/SM / 46 KB = 4; caps oe to curb cross-CTA L1tex-queue spread.)
constexpr int SMEM_FLOATS = 11776;                   // 47,104 bytes

// Persistent scratch (allocation-free __device__ globals). Zero at module
// load; the waiter block re-zeros everything at the end of every run.
__device__ float    g_h[N_ROWS];     // per-row: -N*||e||^2 + 10*diag
__device__ float    g_ysum[H];       // sum_y bi_dec[y][c]
__device__ float    g_scalars[2];    // [0]=Synorm  [1]=sum diag
__device__ unsigned g_maxh;          // monotone-mapped max over rows of h
__device__ unsigned g_maxxn;         // monotone-mapped max over rows of xnorm
__device__ unsigned g_done;          // streaming blocks completed

// Monotone float<->uint mapping (order-preserving for ALL floats).
__device__ __forceinline__ unsigned fmap(float f) {
    unsigned u = __float_as_uint(f);
    return (u & 0x80000000u) ? ~u : (u | 0x80000000u);
}
__device__ __forceinline__ float funmap(unsigned m) {
    return (m & 0x80000000u) ? __uint_as_float(m ^ 0x80000000u)
                             : __uint_as_float(~m);
}

__device__ __forceinline__ float warp_sum(float v) {
    #pragma unroll
    for (int o = 16; o > 0; o >>= 1) v += __shfl_down_sync(0xffffffffu, v, o);
    return v;
}

__global__ __launch_bounds__(THREADS) void fused_kernel(
    const float* __restrict__ enc, const float* __restrict__ dec,
    float* __restrict__ out)
{
    // One static 46 KB block: small slice used, remainder is occupancy ballast.
    __shared__ float smem_all[SMEM_FLOATS];

    const int tid  = threadIdx.x;
    const int lane = tid & 31;
    const int w    = tid >> 5;

    // =====================  WAITER BLOCK  =====================
    if (blockIdx.x == SBLOCKS) {
        float* s_ysm = smem_all;           // [H]
        float* s_red = smem_all + H;       // [WPB]
        float* s_env = smem_all + H + WPB; // [4]

        if (tid == 0) {
            while (__ldcg(&g_done) != (unsigned)SBLOCKS) __nanosleep(128);
        }
        __syncthreads();
        __threadfence();   // acquire: streamers' fenced writes now visible

        // ||Ysum||^2 (+ stash Ysum in shared for the dormant fallback)
        float v = (tid < H) ? __ldcg(&g_ysum[tid]) : 0.0f;
        if (tid < H) s_ysm[tid] = v;
        float ysq = warp_sum(v * v);
        if (lane == 0) s_red[w] = ysq;
        __syncthreads();
        if (tid == 0) {
            float ysn2 = 0.f;
            #pragma unroll
            for (int ww = 0; ww < WPB; ww++) ysn2 += s_red[ww];
            const float syn  = __ldcg(&g_scalars[0]);
            const float mxh  = funmap(g_maxh);
            const float mxxn = funmap(g_maxxn);
            // Global certificate: for every row x,
            //   row_loss <= 5 - syn + maxH + 2*sqrt(maxXnorm*||Ysum||^2)
            const float ub = 5.0f - syn + mxh + 2.0f * sqrtf(mxxn * ysn2)
                           + 16.0f + 1e-5f * (fabsf(mxh) + fabsf(syn));
            s_env[0] = ysn2; s_env[1] = syn; s_env[2] = ub;
        }
        __syncthreads();

        float nce = 0.0f;
        if (s_env[2] > 0.0f) {
            // Exact fallback (dormant on this data; correct in general):
            // one warp per row, strided, dot bi_enc row with shared Ysum.
            const float syn = s_env[1];
            float acc = 0.f;
            for (int r = w; r < N_ROWS; r += WPB) {
                const float4 e  = __ldcg((const float4*)out + r * 32 + lane);
                const float4 yv = ((const float4*)s_ysm)[lane];
                float dp = e.x * yv.x + e.y * yv.y + e.z * yv.z + e.w * yv.w;
                dp = warp_sum(dp);
                if (lane == 0)
                    acc += fmaxf(5.0f - syn + fmaf(2.0f, dp, __ldcg(&g_h[r])), 0.0f);
            }
            if (lane == 0) s_red[w] = acc;
            __syncthreads();
            if (tid == 0) {
                float t = 0.f;
                #pragma unroll
                for (int ww = 0; ww < WPB; ww++) t += s_red[ww];
                s_env[3] = t;
            }
            __syncthreads();
            nce = s_env[3];
        }

        if (tid == 0) {
            out[3 * NHi]     = nce;                                    // nce_loss
            out[3 * NHi + 1] = -__ldcg(&g_scalars[1]) / (float)N_ROWS; // diagonal_loss
        }
        // Re-zero persistent state for the next graph replay.
        if (tid < H) g_ysum[tid] = 0.0f;
        if (tid == H)     g_scalars[0] = 0.0f;
        if (tid == H + 1) g_scalars[1] = 0.0f;
        if (tid == H + 2) { g_maxh = 0u; g_maxxn = 0u; }
        __syncthreads();
        if (tid == 0) atomicExch(&g_done, 0u);
        return;
    }

    // =====================  STREAMING BLOCKS  =====================
    float (*s_ys)[H] = (float(*)[H])smem_all;              // [WPB][H]
    float (*s_sc)[4] = (float(*)[4])(smem_all + WPB * H);  // [WPB][4]

    const int gwarp = blockIdx.x * WPB + w;

    float ys0 = 0.f, ys1 = 0.f, ys2 = 0.f, ys3 = 0.f;
    float ynorm = 0.f, dgsum = 0.f;
    float hp[RPW], xp[RPW];

    #pragma unroll
    for (int i = 0; i < RPW; i++) {
        const int r = gwarp + i * TW;
        // row r = 256 floats = 64 float4; direction halves at +0 / +32
        const float4 a = __ldg((const float4*)enc + r * 64 + lane);
        const float4 b = __ldg((const float4*)enc + r * 64 + 32 + lane);
        const float4 c = __ldg((const float4*)dec + r * 64 + lane);
        const float4 d = __ldg((const float4*)dec + r * 64 + 32 + lane);

        float4 e; e.x = a.x + b.x; e.y = a.y + b.y; e.z = a.z + b.z; e.w = a.w + b.w;
        float4 f; f.x = c.x + d.x; f.y = c.y + d.y; f.z = c.z + d.z; f.w = c.w + d.w;

        ((float4*)out)[r * 32 + lane] = e;                   // bi_enc #1
        __stcs((float4*)out + NHi / 4 + r * 32 + lane, e);   // bi_enc copy
        __stcs((float4*)out + NHi / 2 + r * 32 + lane, f);   // bi_dec

        ys0 += f.x; ys1 += f.y; ys2 += f.z; ys3 += f.w;
        ynorm += f.x * f.x + f.y * f.y + f.z * f.z + f.w * f.w;

        const float en  = e.x * e.x + e.y * e.y + e.z * e.z + e.w * e.w;
        const float gx = e.x - f.x, gy = e.y - f.y, gz = e.z - f.z, gw = e.w - f.w;
        const float dgl = gx * gx + gy * gy + gz * gz + gw * gw;

        dgsum += dgl;
        xp[i] = en;
        hp[i] = fmaf(-(float)N_ROWS, en, 10.0f * dgl);
    }

    // Deferred reductions: 6 independent shfl chains, interleaved by ptxas.
    float h0 = hp[0], h1 = hp[1], x0 = xp[0], x1 = xp[1];
    #pragma unroll
    for (int o = 16; o > 0; o >>= 1) {
        h0    += __shfl_down_sync(0xffffffffu, h0, o);
        h1    += __shfl_down_sync(0xffffffffu, h1, o);
        x0    += __shfl_down_sync(0xffffffffu, x0, o);
        x1    += __shfl_down_sync(0xffffffffu, x1, o);
        ynorm += __shfl_down_sync(0xffffffffu, ynorm, o);
        dgsum += __shfl_down_sync(0xffffffffu, dgsum, o);
    }

    if (lane == 0) {
        g_h[gwarp]      = h0;
        g_h[gwarp + TW] = h1;
        s_sc[w][0] = ynorm; s_sc[w][1] = dgsum;
        s_sc[w][2] = fmaxf(h0, h1); s_sc[w][3] = fmaxf(x0, x1);
    }
    s_ys[w][4 * lane + 0] = ys0;
    s_ys[w][4 * lane + 1] = ys1;
    s_ys[w][4 * lane + 2] = ys2;
    s_ys[w][4 * lane + 3] = ys3;
    __syncthreads();

    if (tid < H) {
        float s = 0.f;
        #pragma unroll
        for (int ww = 0; ww < WPB; ww++) s += s_ys[ww][tid];
        atomicAdd(&g_ysum[tid], s);
    } else if (tid == H) {
        float yn = 0.f, ds = 0.f;
        #pragma unroll
        for (int ww = 0; ww < WPB; ww++) { yn += s_sc[ww][0]; ds += s_sc[ww][1]; }
        atomicAdd(&g_scalars[0], yn);
        atomicAdd(&g_scalars[1], ds);
    } else if (tid == H + 1) {
        float mh = s_sc[0][2], mx = s_sc[0][3];
        #pragma unroll
        for (int ww = 1; ww < WPB; ww++) {
            mh = fmaxf(mh, s_sc[ww][2]); mx = fmaxf(mx, s_sc[ww][3]);
        }
        atomicMax(&g_maxh,  fmap(mh));
        atomicMax(&g_maxxn, fmap(mx));
    }

    // Publish everything (g_h stores + atomics), then signal completion.
    __threadfence();
    __syncthreads();
    if (tid == 0) atomicAdd(&g_done, 1u);
}

extern "C" void kernel_launch(void* const* d_in, const int* in_sizes, int n_in,
                              void* d_out, int out_size) {
    const float* enc = (const float*)d_in[0];
    const float* dec = (const float*)d_in[1];
    float* out = (float*)d_out;

    fused_kernel<<<GRID, THREADS>>>(enc, dec, out);
}

// round 15
// speedup vs baseline: 1.1533x; 1.1533x over previous
#include <cuda_runtime.h>

// Problem constants (fixed by the reference: N=16384, D=2, H=128)
constexpr int N_ROWS = 16384;
constexpr int H      = 128;
constexpr int NHi    = N_ROWS * H;          // floats per [N,H] tensor

constexpr int THREADS = 256;
constexpr int WPB     = 8;                           // warps per block
constexpr int SBLOCKS = 512;                         // streaming blocks
constexpr int TW      = SBLOCKS * WPB;               // 4096 warps
constexpr int RPW     = N_ROWS / TW;                 // 4 rows/warp
constexpr int GRID    = SBLOCKS + 1;                 // + 1 waiter block

// Persistent scratch (allocation-free __device__ globals). Zero at module
// load; the waiter block re-zeros everything at the end of every run.
__device__ float    g_ysum[H];       // sum_y bi_dec[y][c]
__device__ float    g_scalars[2];    // [0]=Synorm  [1]=sum diag
__device__ unsigned g_maxh;          // monotone-mapped max over rows of h
__device__ unsigned g_maxxn;         // monotone-mapped max over rows of xnorm
__device__ unsigned g_done;          // streaming blocks completed

// Monotone float<->uint mapping (order-preserving for ALL floats).
__device__ __forceinline__ unsigned fmap(float f) {
    unsigned u = __float_as_uint(f);
    return (u & 0x80000000u) ? ~u : (u | 0x80000000u);
}
__device__ __forceinline__ float funmap(unsigned m) {
    return (m & 0x80000000u) ? __uint_as_float(m ^ 0x80000000u)
                             : __uint_as_float(~m);
}

__device__ __forceinline__ float warp_sum(float v) {
    #pragma unroll
    for (int o = 16; o > 0; o >>= 1) v += __shfl_down_sync(0xffffffffu, v, o);
    return v;
}

__global__ __launch_bounds__(THREADS) void fused_kernel(
    const float* __restrict__ enc, const float* __restrict__ dec,
    float* __restrict__ out)
{
    const int tid  = threadIdx.x;
    const int lane = tid & 31;
    const int w    = tid >> 5;

    // =====================  WAITER BLOCK  =====================
    if (blockIdx.x == SBLOCKS) {
        __shared__ float s_ysm[H];
        __shared__ float s_red[WPB];
        __shared__ float s_env[4];   // [0]=ysn2 [1]=syn [2]=cert_ub [3]=nce

        if (tid == 0) {
            while (__ldcg(&g_done) != (unsigned)SBLOCKS) __nanosleep(128);
        }
        __syncthreads();
        __threadfence();   // acquire: streamers' published state now visible

        // ||Ysum||^2 (+ stash Ysum in shared for the dormant fallback)
        float v = (tid < H) ? __ldcg(&g_ysum[tid]) : 0.0f;
        if (tid < H) s_ysm[tid] = v;
        float ysq = warp_sum(v * v);
        if (lane == 0) s_red[w] = ysq;
        __syncthreads();
        if (tid == 0) {
            float ysn2 = 0.f;
            #pragma unroll
            for (int ww = 0; ww < WPB; ww++) ysn2 += s_red[ww];
            const float syn  = __ldcg(&g_scalars[0]);
            const float mxh  = funmap(g_maxh);
            const float mxxn = funmap(g_maxxn);
            // Global certificate: for every row x,
            //   row_loss <= 5 - syn + maxH + 2*sqrt(maxXnorm*||Ysum||^2)
            const float ub = 5.0f - syn + mxh + 2.0f * sqrtf(mxxn * ysn2)
                           + 16.0f + 1e-5f * (fabsf(mxh) + fabsf(syn));
            s_env[0] = ysn2; s_env[1] = syn; s_env[2] = ub;
        }
        __syncthreads();

        float nce = 0.0f;
        if (s_env[2] > 0.0f) {
            // Exact fallback (dormant on this data; correct in general):
            // recompute h from bi_enc / bi_dec in out, dot with shared Ysum.
            const float syn = s_env[1];
            float acc = 0.f;
            for (int r = w; r < N_ROWS; r += WPB) {
                const float4 e  = __ldcg((const float4*)out + r * 32 + lane);
                const float4 f  = __ldcg((const float4*)out + NHi / 2 + r * 32 + lane);
                const float4 yv = ((const float4*)s_ysm)[lane];
                const float gx = e.x - f.x, gy = e.y - f.y, gz = e.z - f.z, gw = e.w - f.w;
                const float dgl = gx * gx + gy * gy + gz * gz + gw * gw;
                const float en  = e.x * e.x + e.y * e.y + e.z * e.z + e.w * e.w;
                float q = fmaf(-(float)N_ROWS, en, 10.0f * dgl)
                        + 2.0f * (e.x * yv.x + e.y * yv.y + e.z * yv.z + e.w * yv.w);
                q = warp_sum(q);
                if (lane == 0) acc += fmaxf(5.0f - syn + q, 0.0f);
            }
            if (lane == 0) s_red[w] = acc;
            __syncthreads();
            if (tid == 0) {
                float t = 0.f;
                #pragma unroll
                for (int ww = 0; ww < WPB; ww++) t += s_red[ww];
                s_env[3] = t;
            }
            __syncthreads();
            nce = s_env[3];
        }

        if (tid == 0) {
            out[3 * NHi]     = nce;                                    // nce_loss
            out[3 * NHi + 1] = -__ldcg(&g_scalars[1]) / (float)N_ROWS; // diagonal_loss
        }
        // Re-zero persistent state for the next graph replay.
        if (tid < H) g_ysum[tid] = 0.0f;
        if (tid == H)     g_scalars[0] = 0.0f;
        if (tid == H + 1) g_scalars[1] = 0.0f;
        if (tid == H + 2) { g_maxh = 0u; g_maxxn = 0u; }
        __syncthreads();
        if (tid == 0) atomicExch(&g_done, 0u);
        return;
    }

    // =====================  STREAMING BLOCKS  =====================
    const int gwarp = blockIdx.x * WPB + w;

    float ys0 = 0.f, ys1 = 0.f, ys2 = 0.f, ys3 = 0.f;
    float ynorm = 0.f, dgsum = 0.f;
    float hp[RPW], xp[RPW];

    // Two chunks of 2 rows: 8 front-batched LDG.128 per chunk.
    #pragma unroll
    for (int c0 = 0; c0 < RPW / 2; c0++) {
        const int rA = gwarp + (2 * c0 + 0) * TW;
        const int rB = gwarp + (2 * c0 + 1) * TW;

        const float4 aA = __ldg((const float4*)enc + rA * 64 + lane);
        const float4 bA = __ldg((const float4*)enc + rA * 64 + 32 + lane);
        const float4 cA = __ldg((const float4*)dec + rA * 64 + lane);
        const float4 dA = __ldg((const float4*)dec + rA * 64 + 32 + lane);
        const float4 aB = __ldg((const float4*)enc + rB * 64 + lane);
        const float4 bB = __ldg((const float4*)enc + rB * 64 + 32 + lane);
        const float4 cB = __ldg((const float4*)dec + rB * 64 + lane);
        const float4 dB = __ldg((const float4*)dec + rB * 64 + 32 + lane);

        float4 eA; eA.x = aA.x + bA.x; eA.y = aA.y + bA.y; eA.z = aA.z + bA.z; eA.w = aA.w + bA.w;
        float4 fA; fA.x = cA.x + dA.x; fA.y = cA.y + dA.y; fA.z = cA.z + dA.z; fA.w = cA.w + dA.w;
        float4 eB; eB.x = aB.x + bB.x; eB.y = aB.y + bB.y; eB.z = aB.z + bB.z; eB.w = aB.w + bB.w;
        float4 fB; fB.x = cB.x + dB.x; fB.y = cB.y + dB.y; fB.z = cB.z + dB.z; fB.w = cB.w + dB.w;

        ((float4*)out)[rA * 32 + lane] = eA;                   // bi_enc #1
        ((float4*)out)[rB * 32 + lane] = eB;
        __stcs((float4*)out + NHi / 4 + rA * 32 + lane, eA);   // bi_enc copy
        __stcs((float4*)out + NHi / 4 + rB * 32 + lane, eB);
        __stcs((float4*)out + NHi / 2 + rA * 32 + lane, fA);   // bi_dec
        __stcs((float4*)out + NHi / 2 + rB * 32 + lane, fB);

        ys0 += fA.x + fB.x; ys1 += fA.y + fB.y;
        ys2 += fA.z + fB.z; ys3 += fA.w + fB.w;
        ynorm += fA.x * fA.x + fA.y * fA.y + fA.z * fA.z + fA.w * fA.w
               + fB.x * fB.x + fB.y * fB.y + fB.z * fB.z + fB.w * fB.w;

        const float enA = eA.x * eA.x + eA.y * eA.y + eA.z * eA.z + eA.w * eA.w;
        const float enB = eB.x * eB.x + eB.y * eB.y + eB.z * eB.z + eB.w * eB.w;
        const float gxA = eA.x - fA.x, gyA = eA.y - fA.y, gzA = eA.z - fA.z, gwA = eA.w - fA.w;
        const float gxB = eB.x - fB.x, gyB = eB.y - fB.y, gzB = eB.z - fB.z, gwB = eB.w - fB.w;
        const float dgA = gxA * gxA + gyA * gyA + gzA * gzA + gwA * gwA;
        const float dgB = gxB * gxB + gyB * gyB + gzB * gzB + gwB * gwB;

        dgsum += dgA + dgB;
        xp[2 * c0 + 0] = enA;  xp[2 * c0 + 1] = enB;
        hp[2 * c0 + 0] = fmaf(-(float)N_ROWS, enA, 10.0f * dgA);
        hp[2 * c0 + 1] = fmaf(-(float)N_ROWS, enB, 10.0f * dgB);
    }

    // Deferred reductions: 10 independent shfl chains, interleaved by ptxas.
    #pragma unroll
    for (int o = 16; o > 0; o >>= 1) {
        #pragma unroll
        for (int i = 0; i < RPW; i++) {
            hp[i] += __shfl_down_sync(0xffffffffu, hp[i], o);
            xp[i] += __shfl_down_sync(0xffffffffu, xp[i], o);
        }
        ynorm += __shfl_down_sync(0xffffffffu, ynorm, o);
        dgsum += __shfl_down_sync(0xffffffffu, dgsum, o);
    }

    __shared__ float s_ys[WPB][H];
    __shared__ float s_sc[WPB][4];
    if (lane == 0) {
        float mh = hp[0], mx = xp[0];
        #pragma unroll
        for (int i = 1; i < RPW; i++) { mh = fmaxf(mh, hp[i]); mx = fmaxf(mx, xp[i]); }
        s_sc[w][0] = ynorm; s_sc[w][1] = dgsum; s_sc[w][2] = mh; s_sc[w][3] = mx;
    }
    s_ys[w][4 * lane + 0] = ys0;
    s_ys[w][4 * lane + 1] = ys1;
    s_ys[w][4 * lane + 2] = ys2;
    s_ys[w][4 * lane + 3] = ys3;
    __syncthreads();

    if (tid < H) {
        float s = 0.f;
        #pragma unroll
        for (int ww = 0; ww < WPB; ww++) s += s_ys[ww][tid];
        atomicAdd(&g_ysum[tid], s);
    } else if (tid == H) {
        float yn = 0.f, ds = 0.f;
        #pragma unroll
        for (int ww = 0; ww < WPB; ww++) { yn += s_sc[ww][0]; ds += s_sc[ww][1]; }
        atomicAdd(&g_scalars[0], yn);
        atomicAdd(&g_scalars[1], ds);
    } else if (tid == H + 1) {
        float mh = s_sc[0][2], mx = s_sc[0][3];
        #pragma unroll
        for (int ww = 1; ww < WPB; ww++) {
            mh = fmaxf(mh, s_sc[ww][2]); mx = fmaxf(mx, s_sc[ww][3]);
        }
        atomicMax(&g_maxh,  fmap(mh));
        atomicMax(&g_maxxn, fmap(mx));
    }

    // Publish, then signal completion. bar.sync gives intra-block
    // happens-before; tid0's cumulative fence covers all threads' ops.
    __syncthreads();
    if (tid == 0) {
        __threadfence();
        atomicAdd(&g_done, 1u);
    }
}

extern "C" void kernel_launch(void* const* d_in, const int* in_sizes, int n_in,
                              void* d_out, int out_size) {
    const float* enc = (const float*)d_in[0];
    const float* dec = (const float*)d_in[1];
    float* out = (float*)d_out;

    fused_kernel<<<GRID, THREADS>>>(enc, dec, out);
}